// round 4
// baseline (speedup 1.0000x reference)
#include <cuda_runtime.h>

// Log-sparse causal attention, B=4, L=2048, H=8, E=D=64, fp32.
// Query l attends keys l-d for d in OFF (17 offsets), d <= l.
// Half-warp (16 lanes) processes 4 consecutive queries; the 45 distinct
// K/V rows for the group are each loaded once. Fully fused online form:
// for each row, dot -> butterfly-reduce -> exp -> accumulate into O and sum.
// No stable-softmax max pass (logits bounded ~|10| << fp32 exp overflow).

constexpr int Bc = 4, Lc = 2048, Hc = 8;
constexpr float SCALE = 0.125f;      // 1/sqrt(64), pre-applied to q
constexpr int ROWSTR = Hc * 64;      // 512 elements per l-step

// 45 distinct relative rows e (row = l0 - e) covering all (j in 0..3, d in OFF)
__device__ constexpr int EREL[45] = {
    -3,-2,-1,0,1,2,3,4,5,6,7,8,9,10,11,12,13,
    18,19,20,21, 34,35,36,37, 66,67,68,69,
    130,131,132,133, 258,259,260,261, 514,515,516,517,
    1026,1027,1028,1029
};

// USE[ei][j] = 1 iff query l0+j attends row l0-EREL[ei] (i.e. EREL[ei] = d-j
// for some allowed offset d). Causal validity of that use == (l0 >= EREL[ei]).
__device__ constexpr int USE[45][4] = {
    {0,0,0,1}, {0,0,1,1}, {0,1,1,1}, {1,1,1,1},
    {1,1,1,1}, {1,1,1,1}, {1,1,1,1}, {1,1,1,1},
    {1,1,1,0}, {1,1,0,1}, {1,0,1,0}, {0,1,0,0},
    {1,0,0,0}, {0,0,0,1}, {0,0,1,0}, {0,1,0,0},
    {1,0,0,0},
    {0,0,0,1}, {0,0,1,0}, {0,1,0,0}, {1,0,0,0},
    {0,0,0,1}, {0,0,1,0}, {0,1,0,0}, {1,0,0,0},
    {0,0,0,1}, {0,0,1,0}, {0,1,0,0}, {1,0,0,0},
    {0,0,0,1}, {0,0,1,0}, {0,1,0,0}, {1,0,0,0},
    {0,0,0,1}, {0,0,1,0}, {0,1,0,0}, {1,0,0,0},
    {0,0,0,1}, {0,0,1,0}, {0,1,0,0}, {1,0,0,0},
    {0,0,0,1}, {0,0,1,0}, {0,1,0,0}, {1,0,0,0}
};

__global__ __launch_bounds__(128, 6) void sparse_attn_fused(
    const float* __restrict__ Q,
    const float* __restrict__ K,
    const float* __restrict__ V,
    float* __restrict__ O)
{
    const unsigned FULL = 0xffffffffu;
    const int tid  = threadIdx.x;
    const int warp = tid >> 5;
    const int lane = tid & 31;
    const int half = lane >> 4;
    const int sub  = lane & 15;      // dim slice: floats [4*sub, 4*sub+4)

    // CTA = 32 consecutive queries of one (b,h). grid = 4*8*64 = 2048
    const int cta   = blockIdx.x;
    const int chunk = cta & 63;
    const int bh    = cta >> 6;
    const int h     = bh & 7;
    const int b     = bh >> 3;

    const int l0 = chunk * 32 + warp * 8 + half * 4;   // first of 4 queries

    const int rbase = ((b * Lc + l0) * Hc + h) * 64 + sub * 4;

    // load the 4 query rows, pre-scaled by 1/sqrt(E)
    float4 q[4];
    #pragma unroll
    for (int j = 0; j < 4; j++) {
        float4 t = *reinterpret_cast<const float4*>(Q + rbase + j * ROWSTR);
        t.x *= SCALE; t.y *= SCALE; t.z *= SCALE; t.w *= SCALE;
        q[j] = t;
    }

    float4 acc[4];
    float  sum[4];
    #pragma unroll
    for (int j = 0; j < 4; j++) {
        acc[j] = make_float4(0.f, 0.f, 0.f, 0.f);
        sum[j] = 0.f;
    }

    // ---------- single fused pass over the 45 shared rows ----------
    #pragma unroll
    for (int ei = 0; ei < 45; ei++) {
        const int e = EREL[ei];
        const bool ok = (l0 >= e);                    // == causal validity of every use here
        const int addr = ok ? (rbase - e * ROWSTR) : rbase;  // clamped in-bounds
        const float4 k = *reinterpret_cast<const float4*>(K + addr);
        const float4 v = *reinterpret_cast<const float4*>(V + addr);

        #pragma unroll
        for (int j = 0; j < 4; j++) {
            if (USE[ei][j]) {
                float p = q[j].x * k.x;
                p = fmaf(q[j].y, k.y, p);
                p = fmaf(q[j].z, k.z, p);
                p = fmaf(q[j].w, k.w, p);
                // butterfly over the 16-lane half: every lane gets the full dot
                p += __shfl_xor_sync(FULL, p, 8);
                p += __shfl_xor_sync(FULL, p, 4);
                p += __shfl_xor_sync(FULL, p, 2);
                p += __shfl_xor_sync(FULL, p, 1);
                const float w = ok ? __expf(p) : 0.f;  // exp(pre-scaled logit)
                sum[j] += w;
                acc[j].x = fmaf(w, v.x, acc[j].x);
                acc[j].y = fmaf(w, v.y, acc[j].y);
                acc[j].z = fmaf(w, v.z, acc[j].z);
                acc[j].w = fmaf(w, v.w, acc[j].w);
            }
        }
    }

    // ---------- normalize and store ----------
    #pragma unroll
    for (int j = 0; j < 4; j++) {
        const float inv = __fdividef(1.f, sum[j]);
        float4 o;
        o.x = acc[j].x * inv;
        o.y = acc[j].y * inv;
        o.z = acc[j].z * inv;
        o.w = acc[j].w * inv;
        *reinterpret_cast<float4*>(O + rbase + j * ROWSTR) = o;
    }
}

extern "C" void kernel_launch(void* const* d_in, const int* in_sizes, int n_in,
                              void* d_out, int out_size)
{
    const float* Q = (const float*)d_in[0];
    const float* K = (const float*)d_in[1];
    const float* V = (const float*)d_in[2];
    float* O = (float*)d_out;

    const int nblocks = Bc * Hc * (Lc / 32); // 2048
    sparse_attn_fused<<<nblocks, 128>>>(Q, K, V, O);
}

// round 6
// speedup vs baseline: 1.1135x; 1.1135x over previous
#include <cuda_runtime.h>

// Log-sparse causal attention, B=4, L=2048, H=8, E=D=64, fp32.
// Query l attends keys l-d for d in OFF (17 offsets), d <= l.
// Half-warp (16 lanes) processes QG=4 consecutive queries, sharing K/V row
// loads across the group (45 distinct rows instead of 68).
// Phase 1: batched predicated K loads + per-lane dot partials (max ILP).
// Phase 2: transpose-reduce (15 SHFL -> lane t holds score t), exp2.
// Phase 3: batched V loads, weight broadcasts; softmax sum accumulated here.

constexpr int Bc = 4, Lc = 2048, Hc = 8;
constexpr float SCALE_LOG2E = 0.125f * 1.44269504088896340736f; // 1/sqrt(64) * log2(e)
constexpr int ROWSTR = Hc * 64;      // 512 elements per l-step

// 45 distinct relative rows e (row = l0 - e) covering all (j in 0..3, d in OFF)
__device__ constexpr int EREL[45] = {
    -3,-2,-1,0,1,2,3,4,5,6,7,8,9,10,11,12,13,
    18,19,20,21, 34,35,36,37, 66,67,68,69,
    130,131,132,133, 258,259,260,261, 514,515,516,517,
    1026,1027,1028,1029
};

// TIDX[ei][j] = score-slot t (index into OFF) for query l0+j at row l0-EREL[ei], or -1
__device__ constexpr int TIDX[45][4] = {
    {-1,-1,-1, 0}, {-1,-1, 0, 1}, {-1, 0, 1, 2}, { 0, 1, 2, 3},
    { 1, 2, 3, 4}, { 2, 3, 4, 5}, { 3, 4, 5, 6}, { 4, 5, 6, 7},
    { 5, 6, 7,-1}, { 6, 7,-1, 8}, { 7,-1, 8,-1}, {-1, 8,-1,-1},
    { 8,-1,-1,-1}, {-1,-1,-1, 9}, {-1,-1, 9,-1}, {-1, 9,-1,-1},
    { 9,-1,-1,-1},
    {-1,-1,-1,10}, {-1,-1,10,-1}, {-1,10,-1,-1}, {10,-1,-1,-1},
    {-1,-1,-1,11}, {-1,-1,11,-1}, {-1,11,-1,-1}, {11,-1,-1,-1},
    {-1,-1,-1,12}, {-1,-1,12,-1}, {-1,12,-1,-1}, {12,-1,-1,-1},
    {-1,-1,-1,13}, {-1,-1,13,-1}, {-1,13,-1,-1}, {13,-1,-1,-1},
    {-1,-1,-1,14}, {-1,-1,14,-1}, {-1,14,-1,-1}, {14,-1,-1,-1},
    {-1,-1,-1,15}, {-1,-1,15,-1}, {-1,15,-1,-1}, {15,-1,-1,-1},
    {-1,-1,-1,16}, {-1,-1,16,-1}, {-1,16,-1,-1}, {16,-1,-1,-1}
};

// OFF[u] for u in 0..15: u<8 -> u, else 2^(u-6)+5
__device__ __forceinline__ int off_of_lane(int u) {
    return (u < 8) ? u : ((1 << (u - 6)) + 5);
}

// Transpose-reduce: 16 per-lane partials -> lane u (within 16-lane half)
// holds the full 16-lane sum of value u. 15 SHFLs.
__device__ __forceinline__ float txreduce16(const float* v, int lane) {
    const unsigned FULL = 0xffffffffu;
    const bool b8 = (lane & 8) != 0;
    float w[8];
    #pragma unroll
    for (int i = 0; i < 8; i++) {
        float own = b8 ? v[i + 8] : v[i];
        float oth = b8 ? v[i] : v[i + 8];
        w[i] = own + __shfl_xor_sync(FULL, oth, 8);
    }
    const bool b4 = (lane & 4) != 0;
    float x[4];
    #pragma unroll
    for (int i = 0; i < 4; i++) {
        float own = b4 ? w[i + 4] : w[i];
        float oth = b4 ? w[i] : w[i + 4];
        x[i] = own + __shfl_xor_sync(FULL, oth, 4);
    }
    const bool b2 = (lane & 2) != 0;
    float y[2];
    #pragma unroll
    for (int i = 0; i < 2; i++) {
        float own = b2 ? x[i + 2] : x[i];
        float oth = b2 ? x[i] : x[i + 2];
        y[i] = own + __shfl_xor_sync(FULL, oth, 2);
    }
    const bool b1 = (lane & 1) != 0;
    float own = b1 ? y[1] : y[0];
    float oth = b1 ? y[0] : y[1];
    return own + __shfl_xor_sync(FULL, oth, 1);
}

__global__ __launch_bounds__(128, 5) void sparse_attn_qg4(
    const float* __restrict__ Q,
    const float* __restrict__ K,
    const float* __restrict__ V,
    float* __restrict__ O)
{
    const unsigned FULL = 0xffffffffu;
    const int tid  = threadIdx.x;
    const int warp = tid >> 5;
    const int lane = tid & 31;
    const int half = lane >> 4;
    const int sub  = lane & 15;      // dim slice: floats [4*sub, 4*sub+4)

    // CTA = 32 consecutive queries of one (b,h). grid = 4*8*64 = 2048
    const int cta   = blockIdx.x;
    const int chunk = cta & 63;
    const int bh    = cta >> 6;
    const int h     = bh & 7;
    const int b     = bh >> 3;

    const int lwarp = chunk * 32 + warp * 8;           // warp-uniform base query
    const int l0    = lwarp + half * 4;                // first of this half's 4 queries

    const int rbase = ((b * Lc + l0) * Hc + h) * 64 + sub * 4;

    // load the 4 query rows, pre-scaled by (1/sqrt(E)) * log2(e)
    float4 q0 = *reinterpret_cast<const float4*>(Q + rbase);
    float4 q1 = *reinterpret_cast<const float4*>(Q + rbase + ROWSTR);
    float4 q2 = *reinterpret_cast<const float4*>(Q + rbase + 2 * ROWSTR);
    float4 q3 = *reinterpret_cast<const float4*>(Q + rbase + 3 * ROWSTR);
    q0.x *= SCALE_LOG2E; q0.y *= SCALE_LOG2E; q0.z *= SCALE_LOG2E; q0.w *= SCALE_LOG2E;
    q1.x *= SCALE_LOG2E; q1.y *= SCALE_LOG2E; q1.z *= SCALE_LOG2E; q1.w *= SCALE_LOG2E;
    q2.x *= SCALE_LOG2E; q2.y *= SCALE_LOG2E; q2.z *= SCALE_LOG2E; q2.w *= SCALE_LOG2E;
    q3.x *= SCALE_LOG2E; q3.y *= SCALE_LOG2E; q3.z *= SCALE_LOG2E; q3.w *= SCALE_LOG2E;

    float s[4][17];

    // ---------- Phase 1: partial scores, shared + predicated K row loads ----------
    #pragma unroll
    for (int ei = 0; ei < 45; ei++) {
        const int e = EREL[ei];
        const bool ok = (l0 >= e);
        float4 k = make_float4(0.f, 0.f, 0.f, 0.f);
        if (ok) k = *reinterpret_cast<const float4*>(K + rbase - e * ROWSTR);
        #pragma unroll
        for (int j = 0; j < 4; j++) {
            const int t = TIDX[ei][j];
            if (t >= 0) {
                const float4 qq = (j == 0) ? q0 : (j == 1) ? q1 : (j == 2) ? q2 : q3;
                float p = qq.x * k.x;
                p = fmaf(qq.y, k.y, p);
                p = fmaf(qq.z, k.z, p);
                p = fmaf(qq.w, k.w, p);
                s[j][t] = p;
            }
        }
    }

    // ---------- Phase 2: transpose-reduce + exp (no max pass, no sum pass) ----------
    const int u = sub;                       // lane within half
    const int myoff = off_of_lane(u);        // OFF[u] for u<16
    float ejr[4], e16r[4];

    #pragma unroll
    for (int j = 0; j < 4; j++) {
        float z = txreduce16(&s[j][0], lane);     // lane u holds raw scaled-log2 score u
        const bool valid = (l0 + j >= myoff);
        ejr[j]  = valid ? exp2f(z) : 0.f;
        e16r[j] = 0.f;
    }

    // slot 16 (offset 1029): only for queries >= 1029. Guard must be
    // WARP-UNIFORM (shuffles inside): use lwarp, not l0.
    if (lwarp + 7 >= 1029) {
        #pragma unroll
        for (int j = 0; j < 4; j++) {
            float s16 = s[j][16];
            s16 += __shfl_xor_sync(FULL, s16, 8);
            s16 += __shfl_xor_sync(FULL, s16, 4);
            s16 += __shfl_xor_sync(FULL, s16, 2);
            s16 += __shfl_xor_sync(FULL, s16, 1);
            e16r[j] = (l0 + j >= 1029) ? exp2f(s16) : 0.f;
        }
    }

    // ---------- Phase 3: weighted V accumulation + denominator, shared loads ----------
    float4 a0 = make_float4(0.f, 0.f, 0.f, 0.f);
    float4 a1 = a0, a2 = a0, a3 = a0;
    float sum0 = 0.f, sum1 = 0.f, sum2 = 0.f, sum3 = 0.f;
    const int halfbase = lane & 16;

    #pragma unroll
    for (int ei = 0; ei < 45; ei++) {
        const int e = EREL[ei];
        const bool ok = (l0 >= e);
        float4 v = make_float4(0.f, 0.f, 0.f, 0.f);
        if (ok) v = *reinterpret_cast<const float4*>(V + rbase - e * ROWSTR);
        #pragma unroll
        for (int j = 0; j < 4; j++) {
            const int t = TIDX[ei][j];
            if (t >= 0) {
                float w;
                if (t == 16) w = e16r[j];       // replicated
                else         w = __shfl_sync(FULL, ejr[j], halfbase + t);
                // w == 0 exactly for invalid uses; v == 0 for invalid rows
                float4& a = (j == 0) ? a0 : (j == 1) ? a1 : (j == 2) ? a2 : a3;
                float& sm = (j == 0) ? sum0 : (j == 1) ? sum1 : (j == 2) ? sum2 : sum3;
                sm += w;                         // softmax denominator, free on fma pipe
                a.x = fmaf(w, v.x, a.x);
                a.y = fmaf(w, v.y, a.y);
                a.z = fmaf(w, v.z, a.z);
                a.w = fmaf(w, v.w, a.w);
            }
        }
    }

    const float i0 = __fdividef(1.f, sum0);
    const float i1 = __fdividef(1.f, sum1);
    const float i2 = __fdividef(1.f, sum2);
    const float i3 = __fdividef(1.f, sum3);
    a0.x *= i0; a0.y *= i0; a0.z *= i0; a0.w *= i0;
    a1.x *= i1; a1.y *= i1; a1.z *= i1; a1.w *= i1;
    a2.x *= i2; a2.y *= i2; a2.z *= i2; a2.w *= i2;
    a3.x *= i3; a3.y *= i3; a3.z *= i3; a3.w *= i3;

    *reinterpret_cast<float4*>(O + rbase)              = a0;
    *reinterpret_cast<float4*>(O + rbase + ROWSTR)     = a1;
    *reinterpret_cast<float4*>(O + rbase + 2 * ROWSTR) = a2;
    *reinterpret_cast<float4*>(O + rbase + 3 * ROWSTR) = a3;
}

extern "C" void kernel_launch(void* const* d_in, const int* in_sizes, int n_in,
                              void* d_out, int out_size)
{
    const float* Q = (const float*)d_in[0];
    const float* K = (const float*)d_in[1];
    const float* V = (const float*)d_in[2];
    float* O = (float*)d_out;

    const int nblocks = Bc * Hc * (Lc / 32); // 2048
    sparse_attn_qg4<<<nblocks, 128>>>(Q, K, V, O);
}

// round 7
// speedup vs baseline: 1.2810x; 1.1504x over previous
#include <cuda_runtime.h>

// Log-sparse causal attention, B=4, L=2048, H=8, E=D=64, fp32.
// Query l attends keys l-d for d in OFF (17 offsets), d <= l.
// Half-warp (16 lanes) processes QG=4 consecutive queries, sharing K/V row
// loads across the group (45 distinct rows instead of 68).
// Loads are UNCONDITIONAL clamped-address (predication kills load batching).
// Phase 1: batched K loads + per-lane dot partials (max ILP).
// Phase 2: transpose-reduce (15 SHFL -> lane t holds score t), exp2.
// Phase 3: batched V loads, weight broadcasts; softmax denom accumulated here.

constexpr int Bc = 4, Lc = 2048, Hc = 8;
constexpr float SCALE_LOG2E = 0.125f * 1.44269504088896340736f; // 1/sqrt(64) * log2(e)
constexpr int ROWSTR = Hc * 64;      // 512 elements per l-step

// 45 distinct relative rows e (row = l0 - e) covering all (j in 0..3, d in OFF)
__device__ constexpr int EREL[45] = {
    -3,-2,-1,0,1,2,3,4,5,6,7,8,9,10,11,12,13,
    18,19,20,21, 34,35,36,37, 66,67,68,69,
    130,131,132,133, 258,259,260,261, 514,515,516,517,
    1026,1027,1028,1029
};

// TIDX[ei][j] = score-slot t (index into OFF) for query l0+j at row l0-EREL[ei], or -1
__device__ constexpr int TIDX[45][4] = {
    {-1,-1,-1, 0}, {-1,-1, 0, 1}, {-1, 0, 1, 2}, { 0, 1, 2, 3},
    { 1, 2, 3, 4}, { 2, 3, 4, 5}, { 3, 4, 5, 6}, { 4, 5, 6, 7},
    { 5, 6, 7,-1}, { 6, 7,-1, 8}, { 7,-1, 8,-1}, {-1, 8,-1,-1},
    { 8,-1,-1,-1}, {-1,-1,-1, 9}, {-1,-1, 9,-1}, {-1, 9,-1,-1},
    { 9,-1,-1,-1},
    {-1,-1,-1,10}, {-1,-1,10,-1}, {-1,10,-1,-1}, {10,-1,-1,-1},
    {-1,-1,-1,11}, {-1,-1,11,-1}, {-1,11,-1,-1}, {11,-1,-1,-1},
    {-1,-1,-1,12}, {-1,-1,12,-1}, {-1,12,-1,-1}, {12,-1,-1,-1},
    {-1,-1,-1,13}, {-1,-1,13,-1}, {-1,13,-1,-1}, {13,-1,-1,-1},
    {-1,-1,-1,14}, {-1,-1,14,-1}, {-1,14,-1,-1}, {14,-1,-1,-1},
    {-1,-1,-1,15}, {-1,-1,15,-1}, {-1,15,-1,-1}, {15,-1,-1,-1},
    {-1,-1,-1,16}, {-1,-1,16,-1}, {-1,16,-1,-1}, {16,-1,-1,-1}
};

// OFF[u] for u in 0..15: u<8 -> u, else 2^(u-6)+5
__device__ __forceinline__ int off_of_lane(int u) {
    return (u < 8) ? u : ((1 << (u - 6)) + 5);
}

// Transpose-reduce: 16 per-lane partials -> lane u (within 16-lane half)
// holds the full 16-lane sum of value u. 15 SHFLs.
__device__ __forceinline__ float txreduce16(const float* v, int lane) {
    const unsigned FULL = 0xffffffffu;
    const bool b8 = (lane & 8) != 0;
    float w[8];
    #pragma unroll
    for (int i = 0; i < 8; i++) {
        float own = b8 ? v[i + 8] : v[i];
        float oth = b8 ? v[i] : v[i + 8];
        w[i] = own + __shfl_xor_sync(FULL, oth, 8);
    }
    const bool b4 = (lane & 4) != 0;
    float x[4];
    #pragma unroll
    for (int i = 0; i < 4; i++) {
        float own = b4 ? w[i + 4] : w[i];
        float oth = b4 ? w[i] : w[i + 4];
        x[i] = own + __shfl_xor_sync(FULL, oth, 4);
    }
    const bool b2 = (lane & 2) != 0;
    float y[2];
    #pragma unroll
    for (int i = 0; i < 2; i++) {
        float own = b2 ? x[i + 2] : x[i];
        float oth = b2 ? x[i] : x[i + 2];
        y[i] = own + __shfl_xor_sync(FULL, oth, 2);
    }
    const bool b1 = (lane & 1) != 0;
    float own = b1 ? y[1] : y[0];
    float oth = b1 ? y[0] : y[1];
    return own + __shfl_xor_sync(FULL, oth, 1);
}

__global__ __launch_bounds__(128, 5) void sparse_attn_qg4(
    const float* __restrict__ Q,
    const float* __restrict__ K,
    const float* __restrict__ V,
    float* __restrict__ O)
{
    const unsigned FULL = 0xffffffffu;
    const int tid  = threadIdx.x;
    const int warp = tid >> 5;
    const int lane = tid & 31;
    const int half = lane >> 4;
    const int sub  = lane & 15;      // dim slice: floats [4*sub, 4*sub+4)

    // CTA = 32 consecutive queries of one (b,h). grid = 4*8*64 = 2048
    const int cta   = blockIdx.x;
    const int chunk = cta & 63;
    const int bh    = cta >> 6;
    const int h     = bh & 7;
    const int b     = bh >> 3;

    const int lwarp = chunk * 32 + warp * 8;           // warp-uniform base query
    const int l0    = lwarp + half * 4;                // first of this half's 4 queries

    const int rbase = ((b * Lc + l0) * Hc + h) * 64 + sub * 4;

    // load the 4 query rows, pre-scaled by (1/sqrt(E)) * log2(e)
    float4 q0 = *reinterpret_cast<const float4*>(Q + rbase);
    float4 q1 = *reinterpret_cast<const float4*>(Q + rbase + ROWSTR);
    float4 q2 = *reinterpret_cast<const float4*>(Q + rbase + 2 * ROWSTR);
    float4 q3 = *reinterpret_cast<const float4*>(Q + rbase + 3 * ROWSTR);
    q0.x *= SCALE_LOG2E; q0.y *= SCALE_LOG2E; q0.z *= SCALE_LOG2E; q0.w *= SCALE_LOG2E;
    q1.x *= SCALE_LOG2E; q1.y *= SCALE_LOG2E; q1.z *= SCALE_LOG2E; q1.w *= SCALE_LOG2E;
    q2.x *= SCALE_LOG2E; q2.y *= SCALE_LOG2E; q2.z *= SCALE_LOG2E; q2.w *= SCALE_LOG2E;
    q3.x *= SCALE_LOG2E; q3.y *= SCALE_LOG2E; q3.z *= SCALE_LOG2E; q3.w *= SCALE_LOG2E;

    float s[4][17];

    // ---------- Phase 1: partial scores, shared K row loads (clamped) ----------
    #pragma unroll
    for (int ei = 0; ei < 45; ei++) {
        const int e = EREL[ei];
        const bool ok = (l0 >= e);
        const int addr = ok ? (rbase - e * ROWSTR) : rbase;  // clamped in-bounds
        const float4 k = *reinterpret_cast<const float4*>(K + addr);
        #pragma unroll
        for (int j = 0; j < 4; j++) {
            const int t = TIDX[ei][j];
            if (t >= 0) {
                const float4 qq = (j == 0) ? q0 : (j == 1) ? q1 : (j == 2) ? q2 : q3;
                float p = qq.x * k.x;
                p = fmaf(qq.y, k.y, p);
                p = fmaf(qq.z, k.z, p);
                p = fmaf(qq.w, k.w, p);
                s[j][t] = p;
            }
        }
    }

    // ---------- Phase 2: transpose-reduce + exp (no max pass, no sum pass) ----------
    const int u = sub;                       // lane within half
    const int myoff = off_of_lane(u);        // OFF[u] for u<16
    float ejr[4], e16r[4];

    #pragma unroll
    for (int j = 0; j < 4; j++) {
        float z = txreduce16(&s[j][0], lane);     // lane u holds raw scaled-log2 score u
        const bool valid = (l0 + j >= myoff);
        ejr[j]  = valid ? exp2f(z) : 0.f;
        e16r[j] = 0.f;
    }

    // slot 16 (offset 1029): only for queries >= 1029. Guard is WARP-UNIFORM.
    if (lwarp + 7 >= 1029) {
        #pragma unroll
        for (int j = 0; j < 4; j++) {
            float s16 = s[j][16];
            s16 += __shfl_xor_sync(FULL, s16, 8);
            s16 += __shfl_xor_sync(FULL, s16, 4);
            s16 += __shfl_xor_sync(FULL, s16, 2);
            s16 += __shfl_xor_sync(FULL, s16, 1);
            e16r[j] = (l0 + j >= 1029) ? exp2f(s16) : 0.f;
        }
    }

    // ---------- Phase 3: weighted V accumulation + denominator (clamped loads) ----------
    float4 a0 = make_float4(0.f, 0.f, 0.f, 0.f);
    float4 a1 = a0, a2 = a0, a3 = a0;
    float sum0 = 0.f, sum1 = 0.f, sum2 = 0.f, sum3 = 0.f;
    const int halfbase = lane & 16;

    #pragma unroll
    for (int ei = 0; ei < 45; ei++) {
        const int e = EREL[ei];
        const bool ok = (l0 >= e);
        const int addr = ok ? (rbase - e * ROWSTR) : rbase;  // clamped in-bounds
        const float4 v = *reinterpret_cast<const float4*>(V + addr);
        #pragma unroll
        for (int j = 0; j < 4; j++) {
            const int t = TIDX[ei][j];
            if (t >= 0) {
                float w;
                if (t == 16) w = e16r[j];       // replicated
                else         w = __shfl_sync(FULL, ejr[j], halfbase + t);
                // w == 0 exactly for invalid uses -> clamped v is harmless
                float4& a = (j == 0) ? a0 : (j == 1) ? a1 : (j == 2) ? a2 : a3;
                float& sm = (j == 0) ? sum0 : (j == 1) ? sum1 : (j == 2) ? sum2 : sum3;
                sm += w;                         // softmax denominator, free on fma pipe
                a.x = fmaf(w, v.x, a.x);
                a.y = fmaf(w, v.y, a.y);
                a.z = fmaf(w, v.z, a.z);
                a.w = fmaf(w, v.w, a.w);
            }
        }
    }

    const float i0 = __fdividef(1.f, sum0);
    const float i1 = __fdividef(1.f, sum1);
    const float i2 = __fdividef(1.f, sum2);
    const float i3 = __fdividef(1.f, sum3);
    a0.x *= i0; a0.y *= i0; a0.z *= i0; a0.w *= i0;
    a1.x *= i1; a1.y *= i1; a1.z *= i1; a1.w *= i1;
    a2.x *= i2; a2.y *= i2; a2.z *= i2; a2.w *= i2;
    a3.x *= i3; a3.y *= i3; a3.z *= i3; a3.w *= i3;

    *reinterpret_cast<float4*>(O + rbase)              = a0;
    *reinterpret_cast<float4*>(O + rbase + ROWSTR)     = a1;
    *reinterpret_cast<float4*>(O + rbase + 2 * ROWSTR) = a2;
    *reinterpret_cast<float4*>(O + rbase + 3 * ROWSTR) = a3;
}

extern "C" void kernel_launch(void* const* d_in, const int* in_sizes, int n_in,
                              void* d_out, int out_size)
{
    const float* Q = (const float*)d_in[0];
    const float* K = (const float*)d_in[1];
    const float* V = (const float*)d_in[2];
    float* O = (float*)d_out;

    const int nblocks = Bc * Hc * (Lc / 32); // 2048
    sparse_attn_qg4<<<nblocks, 128>>>(Q, K, V, O);
}

// round 8
// speedup vs baseline: 1.4904x; 1.1635x over previous
#include <cuda_runtime.h>

// Log-sparse causal attention, B=4, L=2048, H=8, E=D=64, fp32.
// Query l attends keys l-d for d in OFF (17 offsets), d <= l.
// Half-warp (16 lanes) processes QG=4 consecutive queries, sharing K/V row
// loads across the group (45 distinct rows instead of 68).
// R3 structure, but the score array is split lo(8)/slot8/hi(8) so the peak
// register live-range drops (~96 -> ~70) and occupancy rises.
// Loads remain UNCONDITIONAL clamped-address (predication kills batching).

constexpr int Bc = 4, Lc = 2048, Hc = 8;
constexpr float SCALE = 0.125f;      // 1/sqrt(64)
constexpr int ROWSTR = Hc * 64;      // 512 elements per l-step

// 45 distinct relative rows e (row = l0 - e) covering all (j in 0..3, d in OFF)
// idx 0..12  : e = -3..9   (completes slots 0..8)
// idx 13..44 : e = 10..1029 (completes slots 9..16)
__device__ constexpr int EREL[45] = {
    -3,-2,-1,0,1,2,3,4,5,6,7,8,9,10,11,12,13,
    18,19,20,21, 34,35,36,37, 66,67,68,69,
    130,131,132,133, 258,259,260,261, 514,515,516,517,
    1026,1027,1028,1029
};

// TIDX[ei][j] = slot t (index into OFF) with OFF[t] = EREL[ei] + j, or -1
__device__ constexpr int TIDX[45][4] = {
    {-1,-1,-1, 0}, {-1,-1, 0, 1}, {-1, 0, 1, 2}, { 0, 1, 2, 3},
    { 1, 2, 3, 4}, { 2, 3, 4, 5}, { 3, 4, 5, 6}, { 4, 5, 6, 7},
    { 5, 6, 7,-1}, { 6, 7,-1, 8}, { 7,-1, 8,-1}, {-1, 8,-1,-1},
    { 8,-1,-1,-1}, {-1,-1,-1, 9}, {-1,-1, 9,-1}, {-1, 9,-1,-1},
    { 9,-1,-1,-1},
    {-1,-1,-1,10}, {-1,-1,10,-1}, {-1,10,-1,-1}, {10,-1,-1,-1},
    {-1,-1,-1,11}, {-1,-1,11,-1}, {-1,11,-1,-1}, {11,-1,-1,-1},
    {-1,-1,-1,12}, {-1,-1,12,-1}, {-1,12,-1,-1}, {12,-1,-1,-1},
    {-1,-1,-1,13}, {-1,-1,13,-1}, {-1,13,-1,-1}, {13,-1,-1,-1},
    {-1,-1,-1,14}, {-1,-1,14,-1}, {-1,14,-1,-1}, {14,-1,-1,-1},
    {-1,-1,-1,15}, {-1,-1,15,-1}, {-1,15,-1,-1}, {15,-1,-1,-1},
    {-1,-1,-1,16}, {-1,-1,16,-1}, {-1,16,-1,-1}, {16,-1,-1,-1}
};

// Transpose-reduce of 8 values over a 16-lane half: lane u ends holding the
// full 16-lane sum of value index (u>>1)&7. 8 SHFLs.
__device__ __forceinline__ float txr8(const float* v, int lane) {
    const unsigned FULL = 0xffffffffu;
    const bool b8 = (lane & 8) != 0;
    float w[4];
    #pragma unroll
    for (int i = 0; i < 4; i++) {
        float own = b8 ? v[i + 4] : v[i];
        float oth = b8 ? v[i] : v[i + 4];
        w[i] = own + __shfl_xor_sync(FULL, oth, 8);
    }
    const bool b4 = (lane & 4) != 0;
    float x[2];
    #pragma unroll
    for (int i = 0; i < 2; i++) {
        float own = b4 ? w[i + 2] : w[i];
        float oth = b4 ? w[i] : w[i + 2];
        x[i] = own + __shfl_xor_sync(FULL, oth, 4);
    }
    const bool b2 = (lane & 2) != 0;
    float own = b2 ? x[1] : x[0];
    float oth = b2 ? x[0] : x[1];
    float y = own + __shfl_xor_sync(FULL, oth, 2);
    y += __shfl_xor_sync(FULL, y, 1);   // bit0 partner holds the same index
    return y;
}

__global__ __launch_bounds__(128, 7) void sparse_attn_split(
    const float* __restrict__ Q,
    const float* __restrict__ K,
    const float* __restrict__ V,
    float* __restrict__ O)
{
    const unsigned FULL = 0xffffffffu;
    const int tid  = threadIdx.x;
    const int warp = tid >> 5;
    const int lane = tid & 31;
    const int half = lane >> 4;
    const int sub  = lane & 15;      // dim slice: floats [4*sub, 4*sub+4)

    // CTA = 32 consecutive queries of one (b,h). grid = 4*8*64 = 2048
    const int cta   = blockIdx.x;
    const int chunk = cta & 63;
    const int bh    = cta >> 6;
    const int h     = bh & 7;
    const int b     = bh >> 3;

    const int l0 = chunk * 32 + warp * 8 + half * 4;   // first of 4 queries

    const int rbase = ((b * Lc + l0) * Hc + h) * 64 + sub * 4;

    // load the 4 query rows
    float4 q0 = *reinterpret_cast<const float4*>(Q + rbase);
    float4 q1 = *reinterpret_cast<const float4*>(Q + rbase + ROWSTR);
    float4 q2 = *reinterpret_cast<const float4*>(Q + rbase + 2 * ROWSTR);
    float4 q3 = *reinterpret_cast<const float4*>(Q + rbase + 3 * ROWSTR);

    const int slot = (sub >> 1) & 7;                 // my lane's value index
    const int offlo = slot;                          // OFF[slot] for lo slots
    const int offhi = (1 << (slot + 3)) + 5;         // OFF[slot+9]: 13,21,...,1029
    const int halfbase = lane & 16;

    float ejlo[4], ejhi[4], e8r[4], inv[4];

    // ---------- Phase 1a: rows e=-3..9 -> slots 0..8 ----------
    {
        float slo[4][8];
        float s8[4];
        #pragma unroll
        for (int ei = 0; ei < 13; ei++) {
            const int e = EREL[ei];
            const bool ok = (l0 >= e);
            const int addr = ok ? (rbase - e * ROWSTR) : rbase;  // clamped
            const float4 k = *reinterpret_cast<const float4*>(K + addr);
            #pragma unroll
            for (int j = 0; j < 4; j++) {
                const int t = TIDX[ei][j];
                if (t >= 0) {
                    const float4 qq = (j == 0) ? q0 : (j == 1) ? q1 : (j == 2) ? q2 : q3;
                    float p = qq.x * k.x;
                    p = fmaf(qq.y, k.y, p);
                    p = fmaf(qq.z, k.z, p);
                    p = fmaf(qq.w, k.w, p);
                    if (t < 8) slo[j][t] = p;
                    else       s8[j] = p;            // t == 8 exactly
                }
            }
        }
        #pragma unroll
        for (int j = 0; j < 4; j++) {
            float zlo = txr8(&slo[j][0], lane);      // lane holds slot (sub>>1)&7
            float z8  = s8[j];                       // full 16-lane butterfly
            z8 += __shfl_xor_sync(FULL, z8, 8);
            z8 += __shfl_xor_sync(FULL, z8, 4);
            z8 += __shfl_xor_sync(FULL, z8, 2);
            z8 += __shfl_xor_sync(FULL, z8, 1);
            ejlo[j] = (l0 + j >= offlo) ? __expf(zlo * SCALE) : 0.f;
            e8r[j]  = (l0 + j >= 9)     ? __expf(z8  * SCALE) : 0.f;
        }
    }

    // ---------- Phase 1b: rows e=10..1029 -> slots 9..16 ----------
    {
        float shi[4][8];
        #pragma unroll
        for (int ei = 13; ei < 45; ei++) {
            const int e = EREL[ei];
            const bool ok = (l0 >= e);
            const int addr = ok ? (rbase - e * ROWSTR) : rbase;  // clamped
            const float4 k = *reinterpret_cast<const float4*>(K + addr);
            #pragma unroll
            for (int j = 0; j < 4; j++) {
                const int t = TIDX[ei][j];
                if (t >= 0) {
                    const float4 qq = (j == 0) ? q0 : (j == 1) ? q1 : (j == 2) ? q2 : q3;
                    float p = qq.x * k.x;
                    p = fmaf(qq.y, k.y, p);
                    p = fmaf(qq.z, k.z, p);
                    p = fmaf(qq.w, k.w, p);
                    shi[j][t - 9] = p;
                }
            }
        }
        #pragma unroll
        for (int j = 0; j < 4; j++) {
            float zhi = txr8(&shi[j][0], lane);
            ejhi[j] = (l0 + j >= offhi) ? __expf(zhi * SCALE) : 0.f;
            // denominator: sum over the 8 distinct lo + 8 distinct hi slots.
            // lanes u, u^1 hold duplicates -> butterfly over xor {2,4,8}.
            float sm = ejlo[j] + ejhi[j];
            sm += __shfl_xor_sync(FULL, sm, 2);
            sm += __shfl_xor_sync(FULL, sm, 4);
            sm += __shfl_xor_sync(FULL, sm, 8);
            inv[j] = __fdividef(1.f, sm + e8r[j]);
        }
    }

    // ---------- Phase 3: weighted V accumulation (clamped loads) ----------
    float4 a0 = make_float4(0.f, 0.f, 0.f, 0.f);
    float4 a1 = a0, a2 = a0, a3 = a0;

    #pragma unroll
    for (int ei = 0; ei < 45; ei++) {
        const int e = EREL[ei];
        const bool ok = (l0 >= e);
        const int addr = ok ? (rbase - e * ROWSTR) : rbase;  // clamped
        const float4 v = *reinterpret_cast<const float4*>(V + addr);
        #pragma unroll
        for (int j = 0; j < 4; j++) {
            const int t = TIDX[ei][j];
            if (t >= 0) {
                float w;
                if (t == 8)      w = e8r[j];                                  // replicated
                else if (t < 8)  w = __shfl_sync(FULL, ejlo[j], halfbase + 2 * t);
                else             w = __shfl_sync(FULL, ejhi[j], halfbase + 2 * (t - 9));
                // w == 0 exactly for invalid uses -> clamped v is harmless
                float4& a = (j == 0) ? a0 : (j == 1) ? a1 : (j == 2) ? a2 : a3;
                a.x = fmaf(w, v.x, a.x);
                a.y = fmaf(w, v.y, a.y);
                a.z = fmaf(w, v.z, a.z);
                a.w = fmaf(w, v.w, a.w);
            }
        }
    }

    a0.x *= inv[0]; a0.y *= inv[0]; a0.z *= inv[0]; a0.w *= inv[0];
    a1.x *= inv[1]; a1.y *= inv[1]; a1.z *= inv[1]; a1.w *= inv[1];
    a2.x *= inv[2]; a2.y *= inv[2]; a2.z *= inv[2]; a2.w *= inv[2];
    a3.x *= inv[3]; a3.y *= inv[3]; a3.z *= inv[3]; a3.w *= inv[3];

    *reinterpret_cast<float4*>(O + rbase)              = a0;
    *reinterpret_cast<float4*>(O + rbase + ROWSTR)     = a1;
    *reinterpret_cast<float4*>(O + rbase + 2 * ROWSTR) = a2;
    *reinterpret_cast<float4*>(O + rbase + 3 * ROWSTR) = a3;
}

extern "C" void kernel_launch(void* const* d_in, const int* in_sizes, int n_in,
                              void* d_out, int out_size)
{
    const float* Q = (const float*)d_in[0];
    const float* K = (const float*)d_in[1];
    const float* V = (const float*)d_in[2];
    float* O = (float*)d_out;

    const int nblocks = Bc * Hc * (Lc / 32); // 2048
    sparse_attn_split<<<nblocks, 128>>>(Q, K, V, O);
}